// round 3
// baseline (speedup 1.0000x reference)
#include <cuda_runtime.h>

#define HH 512
#define WW 512
#define BATCH 16
#define RPB 4        // rows per block
#define PXT 8        // pixels per thread along x
#define TX 64        // threads in x (TX*PXT = 512)
#define TILE_W 516   // 512 + 2 halo each side
#define TILE_STRIDE 520
#define TILE_H (RPB + 4)

__device__ __forceinline__ void ce(float& a, float& b) {
    float t = fminf(a, b);
    b = fmaxf(a, b);
    a = t;
}

// optimal 9-CE sorting network for 5 elements
__device__ __forceinline__ void sort5(float v[5]) {
    ce(v[0], v[1]); ce(v[3], v[4]); ce(v[2], v[4]);
    ce(v[2], v[3]); ce(v[0], v[3]); ce(v[0], v[2]);
    ce(v[1], v[4]); ce(v[1], v[3]); ce(v[1], v[2]);
}

// Batcher odd-even merge of two sorted 5-lists -> sorted 10-list (13 CE)
__device__ __forceinline__ void merge55(const float x[5], const float y[5], float z[10]) {
    float t0 = fminf(x[0], y[0]), t1 = fmaxf(x[0], y[0]);
    float w0 = fminf(x[4], y[4]), w1 = fmaxf(x[4], y[4]);
    float r1 = fminf(w0, t1),     r2 = fmaxf(w0, t1);
    float s0 = fminf(x[2], y[2]), s1 = fmaxf(x[2], y[2]);
    float p0 = t0;
    float p1 = fminf(s0, r1), p2 = fmaxf(s0, r1);
    float p3 = fminf(s1, r2), p4 = fmaxf(s1, r2);
    float p5 = w1;
    float a0 = fminf(x[1], y[1]), a1 = fmaxf(x[1], y[1]);
    float b0 = fminf(x[3], y[3]), b1 = fmaxf(x[3], y[3]);
    float q0 = a0;
    float q1 = fminf(b0, a1), q2 = fmaxf(b0, a1);
    float q3 = b1;
    z[0] = p0;
    z[1] = fminf(q0, p1); z[2] = fmaxf(q0, p1);
    z[3] = fminf(q1, p2); z[4] = fmaxf(q1, p2);
    z[5] = fminf(q2, p3); z[6] = fmaxf(q2, p3);
    z[7] = fminf(q3, p4); z[8] = fmaxf(q3, p4);
    z[9] = p5;
}

// Pruned OEM(10,10): ranks 7..12 (s[0]=s7 ... s[5]=s12) of the merged 20-list.
__device__ __forceinline__ void prune_mid(const float m1[10], const float m2[10], float s[6]) {
    float t1  = fmaxf(m1[0], m2[0]);
    float w0  = fminf(m1[8], m2[8]);
    float r1  = fminf(w0, t1),  r2 = fmaxf(w0, t1);
    float s0  = fminf(m1[4], m2[4]), s1 = fmaxf(m1[4], m2[4]);
    float p2  = fmaxf(s0, r1),  p3 = fminf(s1, r2);
    float t1q = fmaxf(m1[2], m2[2]);
    float w0q = fminf(m1[6], m2[6]);
    float q1  = fminf(w0q, t1q), q2 = fmaxf(w0q, t1q);
    float d4  = fmaxf(q1, p2);
    float d5  = fminf(q2, p3), d6 = fmaxf(q2, p3);

    float t1g = fmaxf(m1[1], m2[1]);
    float w0g = fminf(m1[9], m2[9]);
    float r1g = fminf(w0g, t1g), r2g = fmaxf(w0g, t1g);
    float s0g = fminf(m1[5], m2[5]), s1g = fmaxf(m1[5], m2[5]);
    float p2g = fmaxf(s0g, r1g), p3g = fminf(s1g, r2g);
    float t1h = fmaxf(m1[3], m2[3]);
    float w0h = fminf(m1[7], m2[7]);
    float q1g = fminf(w0h, t1h), q2g = fmaxf(w0h, t1h);
    float g3  = fminf(q1g, p2g), g4 = fmaxf(q1g, p2g);
    float g5  = fminf(q2g, p3g);

    s[0] = fminf(g3, d4); s[1] = fmaxf(g3, d4);
    s[2] = fminf(g4, d5); s[3] = fmaxf(g4, d5);
    s[4] = fminf(g5, d6); s[5] = fmaxf(g5, d6);
}

// 13th smallest of S(20) U E(5), tree-shaped (depth 3 after the maxes).
__device__ __forceinline__ float sel13(const float s[6], const float E[5]) {
    float a = fmaxf(s[4], E[0]);
    float b = fmaxf(s[3], E[1]);
    float c = fmaxf(s[2], E[2]);
    float d = fmaxf(s[1], E[3]);
    float e = fmaxf(s[0], E[4]);
    return fminf(fminf(fminf(a, b), fminf(c, d)), fminf(e, s[5]));
}

// compile-time component select from float4
__device__ __forceinline__ float f4c(const float4& f, int c) {
    return (c == 0) ? f.x : (c == 1) ? f.y : (c == 2) ? f.z : f.w;
}

__global__ __launch_bounds__(TX * RPB)
void Net_29291676958726_kernel(const float* __restrict__ x,
                               const float* __restrict__ noise_var,
                               const float* __restrict__ noise_bias,
                               float* __restrict__ out) {
    __shared__ float tile[TILE_H][TILE_STRIDE];

    const int b   = blockIdx.y;
    const int rb  = blockIdx.x * RPB;
    const int tid = threadIdx.y * TX + threadIdx.x;
    const float* __restrict__ xb_ptr = x + (size_t)b * HH * WW;

    for (int idx = tid; idx < TILE_H * TILE_W; idx += TX * RPB) {
        int r  = idx / TILE_W;
        int c  = idx % TILE_W;
        int gr = rb - 2 + r;
        int gc = c - 2;
        float v = 0.0f;
        if ((unsigned)gr < HH && (unsigned)gc < WW)
            v = xb_ptr[gr * WW + gc];
        tile[r][c] = v;
    }
    __syncthreads();

    const float nv = noise_var[0];
    const float nb = noise_bias[0];

    const int ty    = threadIdx.y;
    const int xbase = threadIdx.x * PXT;   // 32B-aligned in bytes

    float sc[12][5];
    float cen[12];
    float csum[12], csq[12];

    float4 g[5];   // current group of 4 columns, rows ty..ty+4

    // ---- group 0: columns 0..3 ----
#pragma unroll
    for (int k = 0; k < 5; k++)
        g[k] = *(const float4*)&tile[ty + k][xbase + 0];

#pragma unroll
    for (int j = 0; j < 4; j++) {
        float v[5];
#pragma unroll
        for (int k = 0; k < 5; k++) v[k] = f4c(g[k], j);
        csum[j] = ((v[0] + v[1]) + (v[2] + v[3])) + v[4];
        csq[j]  = fmaf(v[0], v[0], fmaf(v[1], v[1], fmaf(v[2], v[2], fmaf(v[3], v[3], v[4] * v[4]))));
        cen[j]  = v[2];
        sort5(v);
#pragma unroll
        for (int k = 0; k < 5; k++) sc[j][k] = v[k];
    }

    float M[10];
    merge55(sc[1], sc[2], M);

    float ws = ((csum[0] + csum[1]) + (csum[2] + csum[3]));
    float wq = ((csq[0]  + csq[1])  + (csq[2]  + csq[3]));

    float2* __restrict__ orow =
        (float2*)(out + (size_t)b * HH * WW + (size_t)(rb + ty) * WW + xbase);

#pragma unroll
    for (int t = 0; t < PXT / 2; t++) {
        // load a fresh group of 4 columns every other pair
        if ((t & 1) == 0) {
            const int cb = 4 + 2 * t;   // t=0 -> cols 4..7, t=2 -> cols 8..11
#pragma unroll
            for (int k = 0; k < 5; k++)
                g[k] = *(const float4*)&tile[ty + k][xbase + cb];
        }

        // new columns 2t+4 and 2t+5 from group components
#pragma unroll
        for (int jj = 0; jj < 2; jj++) {
            const int j = 2 * t + 4 + jj;
            const int c = (2 * t + jj) & 3;
            float v[5];
#pragma unroll
            for (int k = 0; k < 5; k++) v[k] = f4c(g[k], c);
            csum[j] = ((v[0] + v[1]) + (v[2] + v[3])) + v[4];
            csq[j]  = fmaf(v[0], v[0], fmaf(v[1], v[1], fmaf(v[2], v[2], fmaf(v[3], v[3], v[4] * v[4]))));
            cen[j]  = v[2];
            sort5(v);
#pragma unroll
            for (int k = 0; k < 5; k++) sc[j][k] = v[k];
        }

        float N[10];                   // N_t = merge(c_{2t+3}, c_{2t+4}) = M_{t+1}
        merge55(sc[2 * t + 3], sc[2 * t + 4], N);

        float s[6];
        prune_mid(M, N, s);

        // even pixel p = 2t
        float ws_e = ws + csum[2 * t + 4];
        float wq_e = wq + csq[2 * t + 4];
        float var_e = fmaxf((wq_e - ws_e * ws_e * 0.04f) * (1.0f / 24.0f), 0.0f);
        float med_e = sel13(s, sc[2 * t]);
        float xc_e  = cen[2 * t + 2];
        float y_e   = xc_e - nv * __fdividef(xc_e - med_e + nb, var_e + 1e-10f);

        // odd pixel p = 2t+1
        float ws_o = ws_e + csum[2 * t + 5] - csum[2 * t];
        float wq_o = wq_e + csq[2 * t + 5] - csq[2 * t];
        float var_o = fmaxf((wq_o - ws_o * ws_o * 0.04f) * (1.0f / 24.0f), 0.0f);
        float med_o = sel13(s, sc[2 * t + 5]);
        float xc_o  = cen[2 * t + 3];
        float y_o   = xc_o - nv * __fdividef(xc_o - med_o + nb, var_o + 1e-10f);

        orow[t] = make_float2(fmaxf(y_e, 0.0f), fmaxf(y_o, 0.0f));

        ws = ws_o - csum[2 * t + 1];
        wq = wq_o - csq[2 * t + 1];
#pragma unroll
        for (int k = 0; k < 10; k++) M[k] = N[k];
    }
}

extern "C" void kernel_launch(void* const* d_in, const int* in_sizes, int n_in,
                              void* d_out, int out_size) {
    const float* x  = (const float*)d_in[0];
    const float* nv = (const float*)d_in[1];
    const float* nb = (const float*)d_in[2];
    float* out = (float*)d_out;

    dim3 block(TX, RPB);
    dim3 grid(HH / RPB, BATCH);
    Net_29291676958726_kernel<<<grid, block>>>(x, nv, nb, out);
}

// round 4
// speedup vs baseline: 1.0657x; 1.0657x over previous
#include <cuda_runtime.h>

#define HH 512
#define WW 512
#define BATCH 16
#define RPB 4        // rows per block
#define PXT 8        // pixels per thread along x
#define TX 64        // threads in x (TX*PXT = 512)
#define TILE_W 516   // 512 + 2 halo each side
#define TILE_STRIDE 520
#define TILE_H (RPB + 4)
#define NTHREADS (TX * RPB)

__device__ __forceinline__ void ce(float& a, float& b) {
    float t = fminf(a, b);
    b = fmaxf(a, b);
    a = t;
}

// optimal 9-CE sorting network for 5 elements
__device__ __forceinline__ void sort5(float v[5]) {
    ce(v[0], v[1]); ce(v[3], v[4]); ce(v[2], v[4]);
    ce(v[2], v[3]); ce(v[0], v[3]); ce(v[0], v[2]);
    ce(v[1], v[4]); ce(v[1], v[3]); ce(v[1], v[2]);
}

// Batcher odd-even merge of two sorted 5-lists -> sorted 10-list (13 CE)
__device__ __forceinline__ void merge55(const float x[5], const float y[5], float z[10]) {
    float t0 = fminf(x[0], y[0]), t1 = fmaxf(x[0], y[0]);
    float w0 = fminf(x[4], y[4]), w1 = fmaxf(x[4], y[4]);
    float r1 = fminf(w0, t1),     r2 = fmaxf(w0, t1);
    float s0 = fminf(x[2], y[2]), s1 = fmaxf(x[2], y[2]);
    float p0 = t0;
    float p1 = fminf(s0, r1), p2 = fmaxf(s0, r1);
    float p3 = fminf(s1, r2), p4 = fmaxf(s1, r2);
    float p5 = w1;
    float a0 = fminf(x[1], y[1]), a1 = fmaxf(x[1], y[1]);
    float b0 = fminf(x[3], y[3]), b1 = fmaxf(x[3], y[3]);
    float q0 = a0;
    float q1 = fminf(b0, a1), q2 = fmaxf(b0, a1);
    float q3 = b1;
    z[0] = p0;
    z[1] = fminf(q0, p1); z[2] = fmaxf(q0, p1);
    z[3] = fminf(q1, p2); z[4] = fmaxf(q1, p2);
    z[5] = fminf(q2, p3); z[6] = fmaxf(q2, p3);
    z[7] = fminf(q3, p4); z[8] = fmaxf(q3, p4);
    z[9] = p5;
}

// Pruned OEM(10,10): ranks 7..12 (s[0]=s7 ... s[5]=s12) of the merged 20-list.
__device__ __forceinline__ void prune_mid(const float m1[10], const float m2[10], float s[6]) {
    float t1  = fmaxf(m1[0], m2[0]);
    float w0  = fminf(m1[8], m2[8]);
    float r1  = fminf(w0, t1),  r2 = fmaxf(w0, t1);
    float s0  = fminf(m1[4], m2[4]), s1 = fmaxf(m1[4], m2[4]);
    float p2  = fmaxf(s0, r1),  p3 = fminf(s1, r2);
    float t1q = fmaxf(m1[2], m2[2]);
    float w0q = fminf(m1[6], m2[6]);
    float q1  = fminf(w0q, t1q), q2 = fmaxf(w0q, t1q);
    float d4  = fmaxf(q1, p2);
    float d5  = fminf(q2, p3), d6 = fmaxf(q2, p3);

    float t1g = fmaxf(m1[1], m2[1]);
    float w0g = fminf(m1[9], m2[9]);
    float r1g = fminf(w0g, t1g), r2g = fmaxf(w0g, t1g);
    float s0g = fminf(m1[5], m2[5]), s1g = fmaxf(m1[5], m2[5]);
    float p2g = fmaxf(s0g, r1g), p3g = fminf(s1g, r2g);
    float t1h = fmaxf(m1[3], m2[3]);
    float w0h = fminf(m1[7], m2[7]);
    float q1g = fminf(w0h, t1h), q2g = fmaxf(w0h, t1h);
    float g3  = fminf(q1g, p2g), g4 = fmaxf(q1g, p2g);
    float g5  = fminf(q2g, p3g);

    s[0] = fminf(g3, d4); s[1] = fmaxf(g3, d4);
    s[2] = fminf(g4, d5); s[3] = fmaxf(g4, d5);
    s[4] = fminf(g5, d6); s[5] = fmaxf(g5, d6);
}

// 13th smallest of S(20) U E(5), tree-shaped.
__device__ __forceinline__ float sel13(const float s[6], const float E[5]) {
    float a = fmaxf(s[4], E[0]);
    float b = fmaxf(s[3], E[1]);
    float c = fmaxf(s[2], E[2]);
    float d = fmaxf(s[1], E[3]);
    float e = fmaxf(s[0], E[4]);
    return fminf(fminf(fminf(a, b), fminf(c, d)), fminf(e, s[5]));
}

__global__ __launch_bounds__(NTHREADS, 4)
void Net_29291676958726_kernel(const float* __restrict__ x,
                               const float* __restrict__ noise_var,
                               const float* __restrict__ noise_bias,
                               float* __restrict__ out) {
    __shared__ float tile[TILE_H][TILE_STRIDE];

    const int b   = blockIdx.y;
    const int rb  = blockIdx.x * RPB;
    const int tid = threadIdx.y * TX + threadIdx.x;
    const float* __restrict__ xb_ptr = x + (size_t)b * HH * WW;

    // division-free zero-padded tile load: 8 rows, each striped across 256 threads
#pragma unroll
    for (int r = 0; r < TILE_H; r++) {
        const int gr = rb - 2 + r;
        const bool rok = (unsigned)gr < HH;
        const float* __restrict__ src = xb_ptr + (size_t)gr * WW;
#pragma unroll
        for (int cc = 0; cc < 3; cc++) {
            int c = tid + cc * NTHREADS;
            if (c < TILE_W) {
                int gc = c - 2;
                float v = (rok && (unsigned)gc < WW) ? src[gc] : 0.0f;
                tile[r][c] = v;
            }
        }
    }
    __syncthreads();

    const float nv = noise_var[0];
    const float nb = noise_bias[0];

    const int ty    = threadIdx.y;
    const int xbase = threadIdx.x * PXT;   // even -> float2 loads 8B-aligned

    float sc[12][5];
    float cen[12];
    float csum[12], csq[12];

    // prologue: columns 0..3 via two float2 ladders
#pragma unroll
    for (int jp = 0; jp < 2; jp++) {
        float2 gg[5];
#pragma unroll
        for (int k = 0; k < 5; k++)
            gg[k] = *(const float2*)&tile[ty + k][xbase + 2 * jp];
#pragma unroll
        for (int jj = 0; jj < 2; jj++) {
            const int j = 2 * jp + jj;
            float v[5];
#pragma unroll
            for (int k = 0; k < 5; k++) v[k] = jj ? gg[k].y : gg[k].x;
            csum[j] = ((v[0] + v[1]) + (v[2] + v[3])) + v[4];
            csq[j]  = fmaf(v[0], v[0], fmaf(v[1], v[1], fmaf(v[2], v[2], fmaf(v[3], v[3], v[4] * v[4]))));
            cen[j]  = v[2];
            sort5(v);
#pragma unroll
            for (int k = 0; k < 5; k++) sc[j][k] = v[k];
        }
    }

    float M[10];
    merge55(sc[1], sc[2], M);

    float ws = ((csum[0] + csum[1]) + (csum[2] + csum[3]));
    float wq = ((csq[0]  + csq[1])  + (csq[2]  + csq[3]));

    float2* __restrict__ orow =
        (float2*)(out + (size_t)b * HH * WW + (size_t)(rb + ty) * WW + xbase);

#pragma unroll
    for (int t = 0; t < PXT / 2; t++) {
        // columns 2t+4, 2t+5 via one float2 ladder (just-in-time, small live set)
        {
            float2 gg[5];
#pragma unroll
            for (int k = 0; k < 5; k++)
                gg[k] = *(const float2*)&tile[ty + k][xbase + 2 * t + 4];
#pragma unroll
            for (int jj = 0; jj < 2; jj++) {
                const int j = 2 * t + 4 + jj;
                float v[5];
#pragma unroll
                for (int k = 0; k < 5; k++) v[k] = jj ? gg[k].y : gg[k].x;
                csum[j] = ((v[0] + v[1]) + (v[2] + v[3])) + v[4];
                csq[j]  = fmaf(v[0], v[0], fmaf(v[1], v[1], fmaf(v[2], v[2], fmaf(v[3], v[3], v[4] * v[4]))));
                cen[j]  = v[2];
                sort5(v);
#pragma unroll
                for (int k = 0; k < 5; k++) sc[j][k] = v[k];
            }
        }

        float N[10];                   // N_t = merge(c_{2t+3}, c_{2t+4}) = M_{t+1}
        merge55(sc[2 * t + 3], sc[2 * t + 4], N);

        float s[6];
        prune_mid(M, N, s);

        // even pixel p = 2t
        float ws_e = ws + csum[2 * t + 4];
        float wq_e = wq + csq[2 * t + 4];
        float var_e = fmaxf((wq_e - ws_e * ws_e * 0.04f) * (1.0f / 24.0f), 0.0f);
        float med_e = sel13(s, sc[2 * t]);
        float xc_e  = cen[2 * t + 2];
        float y_e   = xc_e - nv * __fdividef(xc_e - med_e + nb, var_e + 1e-10f);

        // odd pixel p = 2t+1
        float ws_o = ws_e + csum[2 * t + 5] - csum[2 * t];
        float wq_o = wq_e + csq[2 * t + 5] - csq[2 * t];
        float var_o = fmaxf((wq_o - ws_o * ws_o * 0.04f) * (1.0f / 24.0f), 0.0f);
        float med_o = sel13(s, sc[2 * t + 5]);
        float xc_o  = cen[2 * t + 3];
        float y_o   = xc_o - nv * __fdividef(xc_o - med_o + nb, var_o + 1e-10f);

        orow[t] = make_float2(fmaxf(y_e, 0.0f), fmaxf(y_o, 0.0f));

        ws = ws_o - csum[2 * t + 1];
        wq = wq_o - csq[2 * t + 1];
#pragma unroll
        for (int k = 0; k < 10; k++) M[k] = N[k];
    }
}

extern "C" void kernel_launch(void* const* d_in, const int* in_sizes, int n_in,
                              void* d_out, int out_size) {
    const float* x  = (const float*)d_in[0];
    const float* nv = (const float*)d_in[1];
    const float* nb = (const float*)d_in[2];
    float* out = (float*)d_out;

    dim3 block(TX, RPB);
    dim3 grid(HH / RPB, BATCH);
    Net_29291676958726_kernel<<<grid, block>>>(x, nv, nb, out);
}

// round 5
// speedup vs baseline: 1.0927x; 1.0253x over previous
#include <cuda_runtime.h>

#define HH 512
#define WW 512
#define BATCH 16
#define RPB 4        // rows per block
#define PXT 8        // pixels per thread along x
#define TX 64        // threads in x (TX*PXT = 512)
#define TILE_W 516   // 512 + 2 halo each side
#define TILE_STRIDE 520
#define TILE_H (RPB + 4)
#define NTHREADS (TX * RPB)

__device__ __forceinline__ void ce(float& a, float& b) {
    float t = fminf(a, b);
    b = fmaxf(a, b);
    a = t;
}

// optimal 9-CE sorting network for 5 elements
__device__ __forceinline__ void sort5(float v[5]) {
    ce(v[0], v[1]); ce(v[3], v[4]); ce(v[2], v[4]);
    ce(v[2], v[3]); ce(v[0], v[3]); ce(v[0], v[2]);
    ce(v[1], v[4]); ce(v[1], v[3]); ce(v[1], v[2]);
}

// Batcher odd-even merge of two sorted 5-lists -> sorted 10-list (13 CE)
__device__ __forceinline__ void merge55(const float x[5], const float y[5], float z[10]) {
    float t0 = fminf(x[0], y[0]), t1 = fmaxf(x[0], y[0]);
    float w0 = fminf(x[4], y[4]), w1 = fmaxf(x[4], y[4]);
    float r1 = fminf(w0, t1),     r2 = fmaxf(w0, t1);
    float s0 = fminf(x[2], y[2]), s1 = fmaxf(x[2], y[2]);
    float p0 = t0;
    float p1 = fminf(s0, r1), p2 = fmaxf(s0, r1);
    float p3 = fminf(s1, r2), p4 = fmaxf(s1, r2);
    float p5 = w1;
    float a0 = fminf(x[1], y[1]), a1 = fmaxf(x[1], y[1]);
    float b0 = fminf(x[3], y[3]), b1 = fmaxf(x[3], y[3]);
    float q0 = a0;
    float q1 = fminf(b0, a1), q2 = fmaxf(b0, a1);
    float q3 = b1;
    z[0] = p0;
    z[1] = fminf(q0, p1); z[2] = fmaxf(q0, p1);
    z[3] = fminf(q1, p2); z[4] = fmaxf(q1, p2);
    z[5] = fminf(q2, p3); z[6] = fmaxf(q2, p3);
    z[7] = fminf(q3, p4); z[8] = fmaxf(q3, p4);
    z[9] = p5;
}

// Pruned OEM(10,10): ranks 7..12 (s[0]=s7 ... s[5]=s12) of the merged 20-list.
__device__ __forceinline__ void prune_mid(const float m1[10], const float m2[10], float s[6]) {
    float t1  = fmaxf(m1[0], m2[0]);
    float w0  = fminf(m1[8], m2[8]);
    float r1  = fminf(w0, t1),  r2 = fmaxf(w0, t1);
    float s0  = fminf(m1[4], m2[4]), s1 = fmaxf(m1[4], m2[4]);
    float p2  = fmaxf(s0, r1),  p3 = fminf(s1, r2);
    float t1q = fmaxf(m1[2], m2[2]);
    float w0q = fminf(m1[6], m2[6]);
    float q1  = fminf(w0q, t1q), q2 = fmaxf(w0q, t1q);
    float d4  = fmaxf(q1, p2);
    float d5  = fminf(q2, p3), d6 = fmaxf(q2, p3);

    float t1g = fmaxf(m1[1], m2[1]);
    float w0g = fminf(m1[9], m2[9]);
    float r1g = fminf(w0g, t1g), r2g = fmaxf(w0g, t1g);
    float s0g = fminf(m1[5], m2[5]), s1g = fmaxf(m1[5], m2[5]);
    float p2g = fmaxf(s0g, r1g), p3g = fminf(s1g, r2g);
    float t1h = fmaxf(m1[3], m2[3]);
    float w0h = fminf(m1[7], m2[7]);
    float q1g = fminf(w0h, t1h), q2g = fmaxf(w0h, t1h);
    float g3  = fminf(q1g, p2g), g4 = fmaxf(q1g, p2g);
    float g5  = fminf(q2g, p3g);

    s[0] = fminf(g3, d4); s[1] = fmaxf(g3, d4);
    s[2] = fminf(g4, d5); s[3] = fmaxf(g4, d5);
    s[4] = fminf(g5, d6); s[5] = fmaxf(g5, d6);
}

// 13th smallest of S(20) U E(5), tree-shaped.
__device__ __forceinline__ float sel13(const float s[6], const float E[5]) {
    float a = fmaxf(s[4], E[0]);
    float b = fmaxf(s[3], E[1]);
    float c = fmaxf(s[2], E[2]);
    float d = fmaxf(s[1], E[3]);
    float e = fmaxf(s[0], E[4]);
    return fminf(fminf(fminf(a, b), fminf(c, d)), fminf(e, s[5]));
}

__device__ __forceinline__ float sum5(const float v[5]) {
    return ((v[0] + v[1]) + (v[2] + v[3])) + v[4];
}
__device__ __forceinline__ float sq5(const float v[5]) {
    return fmaf(v[0], v[0], fmaf(v[1], v[1], fmaf(v[2], v[2], fmaf(v[3], v[3], v[4] * v[4]))));
}

__global__ __launch_bounds__(NTHREADS, 4)
void Net_29291676958726_kernel(const float* __restrict__ x,
                               const float* __restrict__ noise_var,
                               const float* __restrict__ noise_bias,
                               float* __restrict__ out) {
    __shared__ float tile[TILE_H][TILE_STRIDE];

    const int b   = blockIdx.y;
    const int rb  = blockIdx.x * RPB;
    const int tid = threadIdx.y * TX + threadIdx.x;
    const float* __restrict__ xb_ptr = x + (size_t)b * HH * WW;

    // division-free zero-padded tile load
#pragma unroll
    for (int r = 0; r < TILE_H; r++) {
        const int gr = rb - 2 + r;
        const bool rok = (unsigned)gr < HH;
        const float* __restrict__ src = xb_ptr + (size_t)gr * WW;
#pragma unroll
        for (int cc = 0; cc < 3; cc++) {
            int c = tid + cc * NTHREADS;
            if (c < TILE_W) {
                int gc = c - 2;
                tile[r][c] = (rok && (unsigned)gc < WW) ? src[gc] : 0.0f;
            }
        }
    }
    __syncthreads();

    const float nv = noise_var[0];
    const float nb = noise_bias[0];

    const int ty    = threadIdx.y;
    const int xbase = threadIdx.x * PXT;

    // Rotating live state (5 sorted columns + merge M + a few scalars)
    float Ecur[5], Enext[5], C3[5];   // sorted columns 2t, 2t+2, 2t+3
    float M[10];                      // merge of columns 2t+1, 2t+2
    float sM, qM;                     // sum/sumsq over M's two columns
    float s3, q3;                     // sum/sumsq of column 2t+3
    float cenE, cenO;                 // centers of columns 2t+2, 2t+3

    // ---- prologue: columns 0..3 ----
    {
        float c0[5], c1[5], c2[5], c3v[5];
#pragma unroll
        for (int jp = 0; jp < 2; jp++) {
            float2 gg[5];
#pragma unroll
            for (int k = 0; k < 5; k++)
                gg[k] = *(const float2*)&tile[ty + k][xbase + 2 * jp];
#pragma unroll
            for (int k = 0; k < 5; k++) {
                (jp ? c2 : c0)[k] = gg[k].x;
                (jp ? c3v : c1)[k] = gg[k].y;
            }
        }
        sM   = sum5(c1) + sum5(c2);
        qM   = sq5(c1) + sq5(c2);
        s3   = sum5(c3v);
        q3   = sq5(c3v);
        cenE = c2[2];
        cenO = c3v[2];
        sort5(c0); sort5(c1); sort5(c2); sort5(c3v);
#pragma unroll
        for (int k = 0; k < 5; k++) { Ecur[k] = c0[k]; Enext[k] = c2[k]; C3[k] = c3v[k]; }
        merge55(c1, c2, M);
    }

    float2* __restrict__ orow =
        (float2*)(out + (size_t)b * HH * WW + (size_t)(rb + ty) * WW + xbase);

#pragma unroll
    for (int t = 0; t < PXT / 2; t++) {
        // fresh columns 2t+4, 2t+5
        float v4[5], v5[5];
        {
            float2 gg[5];
#pragma unroll
            for (int k = 0; k < 5; k++)
                gg[k] = *(const float2*)&tile[ty + k][xbase + 2 * t + 4];
#pragma unroll
            for (int k = 0; k < 5; k++) { v4[k] = gg[k].x; v5[k] = gg[k].y; }
        }
        float s4 = sum5(v4), q4 = sq5(v4);
        float s5 = sum5(v5), q5 = sq5(v5);
        float cen4 = v4[2], cen5 = v5[2];
        sort5(v4); sort5(v5);

        float N[10];                   // merge(col 2t+3, col 2t+4) = next M
        merge55(C3, v4, N);

        float s[6];
        prune_mid(M, N, s);

        float sN = s3 + s4;
        float qN = q3 + q4;

        // even pixel p = 2t: window = Ecur + M-cols + N-cols
        float sE = sum5(Ecur), qE = sq5(Ecur);
        float sum_e = sE + sM + sN;
        float sq_e  = qE + qM + qN;
        float var_e = fmaxf((sq_e - sum_e * sum_e * 0.04f) * (1.0f / 24.0f), 0.0f);
        float med_e = sel13(s, Ecur);
        float y_e   = cenE - nv * __fdividef(cenE - med_e + nb, var_e + 1e-10f);

        // odd pixel p = 2t+1: window = M-cols + N-cols + col 2t+5
        float sum_o = sM + sN + s5;
        float sq_o  = qM + qN + q5;
        float var_o = fmaxf((sq_o - sum_o * sum_o * 0.04f) * (1.0f / 24.0f), 0.0f);
        float med_o = sel13(s, v5);
        float y_o   = cenO - nv * __fdividef(cenO - med_o + nb, var_o + 1e-10f);

        orow[t] = make_float2(fmaxf(y_e, 0.0f), fmaxf(y_o, 0.0f));

        // rotate state for pair t+1
#pragma unroll
        for (int k = 0; k < 5; k++) { Ecur[k] = Enext[k]; Enext[k] = v4[k]; C3[k] = v5[k]; }
#pragma unroll
        for (int k = 0; k < 10; k++) M[k] = N[k];
        sM = sN; qM = qN;
        s3 = s5; q3 = q5;
        cenE = cen4; cenO = cen5;
    }
}

extern "C" void kernel_launch(void* const* d_in, const int* in_sizes, int n_in,
                              void* d_out, int out_size) {
    const float* x  = (const float*)d_in[0];
    const float* nv = (const float*)d_in[1];
    const float* nb = (const float*)d_in[2];
    float* out = (float*)d_out;

    dim3 block(TX, RPB);
    dim3 grid(HH / RPB, BATCH);
    Net_29291676958726_kernel<<<grid, block>>>(x, nv, nb, out);
}